// round 11
// baseline (speedup 1.0000x reference)
#include <cuda_runtime.h>
#include <cstdint>

#define NBLK 296            // 148 SMs x 2 CTAs: exactly one wave
#define NTHR 256
#define NWARP (NTHR / 32)
#define NSTAGE 2
#define ARRS 11
#define STAGE_F4 (ARRS * NTHR)                 // float4 slots per stage
#define SMEM_BYTES (NSTAGE * STAGE_F4 * 16)    // 90112 bytes per CTA

// Per-block partial sums (deterministic reduction, no data atomics).
__device__ float g_part_p[NBLK];
__device__ float g_part_ll[NBLK];
__device__ float g_part_np[NBLK];
__device__ unsigned g_ticket = 0;   // self-resetting last-block-done counter

__device__ __forceinline__ float frcp(float x) {
    float y;
    asm("rcp.approx.f32 %0, %1;" : "=f"(y) : "f"(x));
    return y;
}
__device__ __forceinline__ float fex2(float x) {
    float y;
    asm("ex2.approx.f32 %0, %1;" : "=f"(y) : "f"(x));
    return y;
}

struct Acc { float p, ll, np; };

// Binned mixture probability, log2-domain:
//   sigmoid(u)-sigmoid(l) = (el-eu)/((1+eu)(1+el)),
//   eu = 2^(a-b), el = 2^(a+b), a=(m-t)*inv*log2e, b=HB*inv*log2e.
// Saturation: overflow -> den inf -> rcp 0 -> 0/NaN; fmax(.,EPS)=EPS,
// matching the reference's clamped regime.
__device__ __forceinline__ float comp_prob(float m, float t, float s) {
    const float EPS = 1e-8f;
    const float HB  = 0.05f;
    const float L2E = 1.4426950408889634f;
    float il = frcp(s + EPS) * L2E;
    float a  = (m - t) * il;
    float b  = HB * il;
    float eu = fex2(a - b);
    float el = fex2(a + b);
    float den = frcp((1.f + eu) * (1.f + el));
    return fmaxf((el - eu) * den, EPS);
}

__device__ __forceinline__ void process_elem(
    float p, float t,
    float m0, float s0, float w0,
    float m1, float s1, float w1,
    float m2, float s2, float w2,
    Acc& a)
{
    const float EPS = 1e-8f;

    float lik = w0 * comp_prob(m0, t, s0);
    lik = fmaf(w1, comp_prob(m1, t, s1), lik);
    lik = fmaf(w2, comp_prob(m2, t, s2), lik);

    bool paid = (t > 0.f);
    float ll = __logf(lik + EPS);
    if (paid) { a.ll += ll; a.np += 1.f; }

    float q = paid ? p : (1.f - p);
    a.p -= fmaxf(__logf(q), -100.f);
}

// 16-byte cp.async (.cg: L2-only fill, no L1 pollution, no RF transit).
__device__ __forceinline__ void cpa16(uint32_t dst, const float4* src) {
    asm volatile("cp.async.cg.shared.global [%0], [%1], 16;"
                 :: "r"(dst), "l"(src) : "memory");
}

__global__ void __launch_bounds__(NTHR, 2) zimol_fused(
    const float* __restrict__ pp, const float* __restrict__ mu,
    const float* __restrict__ sg, const float* __restrict__ wt,
    const float* __restrict__ tv, float* __restrict__ out, int B)
{
    extern __shared__ float4 sbuf[];   // [NSTAGE][ARRS][NTHR]

    const int nvec4  = B >> 2;                        // float4 elements per row
    const int ntiles = (nvec4 + NTHR - 1) / NTHR;     // tiles of NTHR float4
    const int tid = threadIdx.x;
    const int bid = blockIdx.x;
    const int mk  = (bid < ntiles) ? (ntiles - bid + NBLK - 1) / NBLK : 0;

    const float4* pp4 = reinterpret_cast<const float4*>(pp);
    const float4* tv4 = reinterpret_cast<const float4*>(tv);
    const float4* mu4 = reinterpret_cast<const float4*>(mu);
    const float4* sg4 = reinterpret_cast<const float4*>(sg);
    const float4* wt4 = reinterpret_cast<const float4*>(wt);

    const uint32_t sbase =
        (uint32_t)__cvta_generic_to_shared(sbuf) + (uint32_t)tid * 16u;

    Acc a = {0.f, 0.f, 0.f};

    // Issue one stage's 11 x 16B copies into this thread's private slots.
    auto issue = [&](int t) {
        int v = (bid + t * NBLK) * NTHR + tid;
        if (v < nvec4) {
            uint32_t d = sbase + (uint32_t)(t & (NSTAGE - 1)) * (uint32_t)(STAGE_F4 * 16);
            cpa16(d + 0u  * (NTHR * 16u), pp4 + v);
            cpa16(d + 1u  * (NTHR * 16u), tv4 + v);
            cpa16(d + 2u  * (NTHR * 16u), mu4 + v);
            cpa16(d + 3u  * (NTHR * 16u), mu4 + nvec4 + v);
            cpa16(d + 4u  * (NTHR * 16u), mu4 + 2 * nvec4 + v);
            cpa16(d + 5u  * (NTHR * 16u), sg4 + v);
            cpa16(d + 6u  * (NTHR * 16u), sg4 + nvec4 + v);
            cpa16(d + 7u  * (NTHR * 16u), sg4 + 2 * nvec4 + v);
            cpa16(d + 8u  * (NTHR * 16u), wt4 + v);
            cpa16(d + 9u  * (NTHR * 16u), wt4 + nvec4 + v);
            cpa16(d + 10u * (NTHR * 16u), wt4 + 2 * nvec4 + v);
        }
    };

    auto compute_stage = [&](int k) {
        int v = (bid + k * NBLK) * NTHR + tid;
        if (v >= nvec4) return;
        const float4* sb = sbuf + (k & (NSTAGE - 1)) * STAGE_F4 + tid;
        float4 P  = sb[0 * NTHR], T  = sb[1 * NTHR];
        float4 M0 = sb[2 * NTHR], M1 = sb[3 * NTHR], M2 = sb[4 * NTHR];
        float4 S0 = sb[5 * NTHR], S1 = sb[6 * NTHR], S2 = sb[7 * NTHR];
        float4 W0 = sb[8 * NTHR], W1 = sb[9 * NTHR], W2 = sb[10 * NTHR];
        process_elem(P.x, T.x, M0.x, S0.x, W0.x,
                     M1.x, S1.x, W1.x, M2.x, S2.x, W2.x, a);
        process_elem(P.y, T.y, M0.y, S0.y, W0.y,
                     M1.y, S1.y, W1.y, M2.y, S2.y, W2.y, a);
        process_elem(P.z, T.z, M0.z, S0.z, W0.z,
                     M1.z, S1.z, W1.z, M2.z, S2.z, W2.z, a);
        process_elem(P.w, T.w, M0.w, S0.w, W0.w,
                     M1.w, S1.w, W1.w, M2.w, S2.w, W2.w, a);
    };

    // ---- Double-buffered cp.async pipeline (per-thread groups, no barriers) ----
    if (mk > 0) issue(0);
    asm volatile("cp.async.commit_group;" ::: "memory");
    for (int k = 0; k < mk; k++) {
        if (k + 1 < mk) issue(k + 1);
        asm volatile("cp.async.commit_group;" ::: "memory");
        asm volatile("cp.async.wait_group 1;" ::: "memory");  // stage k complete
        compute_stage(k);
    }

    // Scalar tail (B not divisible by 4) — robustness; no-op for B = 4M.
    int tail = B & 3;
    if (tail) {
        int base = nvec4 << 2;
        int idx = bid * NTHR + tid;
        if (idx < tail) {
            int j = base + idx;
            process_elem(pp[j], tv[j],
                         mu[0 * B + j], sg[0 * B + j], wt[0 * B + j],
                         mu[1 * B + j], sg[1 * B + j], wt[1 * B + j],
                         mu[2 * B + j], sg[2 * B + j], wt[2 * B + j], a);
        }
    }

    // ---- Block reduction (all float, shuffle + tiny smem) ----
    #pragma unroll
    for (int o = 16; o > 0; o >>= 1) {
        a.p  += __shfl_down_sync(0xffffffffu, a.p,  o);
        a.ll += __shfl_down_sync(0xffffffffu, a.ll, o);
        a.np += __shfl_down_sync(0xffffffffu, a.np, o);
    }

    __shared__ float shp[NWARP], shl[NWARP], shn[NWARP];
    __shared__ bool s_last;
    int wid  = tid >> 5;
    int lane = tid & 31;
    if (lane == 0) { shp[wid] = a.p; shl[wid] = a.ll; shn[wid] = a.np; }
    __syncthreads();

    if (tid == 0) {
        float vp = 0.f, vl = 0.f, vn = 0.f;
        #pragma unroll
        for (int k = 0; k < NWARP; k++) { vp += shp[k]; vl += shl[k]; vn += shn[k]; }
        g_part_p[bid]  = vp;
        g_part_ll[bid] = vl;
        g_part_np[bid] = vn;
        __threadfence();
        unsigned t = atomicAdd(&g_ticket, 1u);
        s_last = (t == (unsigned)(NBLK - 1));
        if (s_last) g_ticket = 0u;   // self-reset: deterministic across replays
    }
    __syncthreads();

    // ---- Last block finalizes (float, 296 partials) ----
    if (s_last) {
        float sp = 0.f, sl = 0.f, sn = 0.f;
        for (int k = tid; k < NBLK; k += NTHR) {
            sp += g_part_p[k];
            sl += g_part_ll[k];
            sn += g_part_np[k];
        }
        #pragma unroll
        for (int o = 16; o > 0; o >>= 1) {
            sp += __shfl_down_sync(0xffffffffu, sp, o);
            sl += __shfl_down_sync(0xffffffffu, sl, o);
            sn += __shfl_down_sync(0xffffffffu, sn, o);
        }
        if (lane == 0) { shp[wid] = sp; shl[wid] = sl; shn[wid] = sn; }
        __syncthreads();
        if (tid == 0) {
            float vp = 0.f, vl = 0.f, vn = 0.f;
            #pragma unroll
            for (int k = 0; k < NWARP; k++) { vp += shp[k]; vl += shl[k]; vn += shn[k]; }
            float purchase = vp / (float)B;
            float ltv = (vn > 0.f) ? -(vl / fmaxf(vn, 1.f)) : 0.f;
            out[0] = purchase + ltv;
        }
    }
}

extern "C" void kernel_launch(void* const* d_in, const int* in_sizes, int n_in,
                              void* d_out, int out_size)
{
    const float* pp = (const float*)d_in[0];  // predicted_purchase_prob (B,)
    const float* mu = (const float*)d_in[1];  // mu     (K,B)
    const float* sg = (const float*)d_in[2];  // sigma  (K,B)
    const float* wt = (const float*)d_in[3];  // weight (K,B)
    const float* tv = (const float*)d_in[4];  // true_values (B,)
    int B = in_sizes[0];

    // Opt-in to 88 KB dynamic smem per CTA (idempotent; not a stream op).
    cudaFuncSetAttribute(zimol_fused,
                         cudaFuncAttributeMaxDynamicSharedMemorySize, SMEM_BYTES);
    zimol_fused<<<NBLK, NTHR, SMEM_BYTES>>>(pp, mu, sg, wt, tv, (float*)d_out, B);
}

// round 12
// speedup vs baseline: 1.0916x; 1.0916x over previous
#include <cuda_runtime.h>
#include <cstdint>

#define NBLK 148            // 1 CTA per SM, exactly one wave
#define NTHR 512
#define NWARP (NTHR / 32)
#define NSTAGE 4
#define ARRS 11
#define STAGE_F2 (ARRS * NTHR)                 // float2 slots per stage
#define STAGE_BYTES (STAGE_F2 * 8)             // 45056
#define SMEM_BYTES (NSTAGE * STAGE_BYTES)      // 180224

// Per-block partial sums (deterministic reduction, no data atomics).
__device__ float g_part_p[NBLK];
__device__ float g_part_ll[NBLK];
__device__ float g_part_np[NBLK];
__device__ unsigned g_ticket = 0;   // self-resetting last-block-done counter

__device__ __forceinline__ float frcp(float x) {
    float y;
    asm("rcp.approx.f32 %0, %1;" : "=f"(y) : "f"(x));
    return y;
}
__device__ __forceinline__ float fex2(float x) {
    float y;
    asm("ex2.approx.f32 %0, %1;" : "=f"(y) : "f"(x));
    return y;
}

struct Acc { float p, ll, np; };

// Binned mixture probability, log2-domain (saturation matches reference clamp).
__device__ __forceinline__ float comp_prob(float m, float t, float s) {
    const float EPS = 1e-8f;
    const float HB  = 0.05f;
    const float L2E = 1.4426950408889634f;
    float il = frcp(s + EPS) * L2E;
    float a  = (m - t) * il;
    float b  = HB * il;
    float eu = fex2(a - b);
    float el = fex2(a + b);
    float den = frcp((1.f + eu) * (1.f + el));
    return fmaxf((el - eu) * den, EPS);
}

__device__ __forceinline__ void process_elem(
    float p, float t,
    float m0, float s0, float w0,
    float m1, float s1, float w1,
    float m2, float s2, float w2,
    Acc& a)
{
    const float EPS = 1e-8f;

    float lik = w0 * comp_prob(m0, t, s0);
    lik = fmaf(w1, comp_prob(m1, t, s1), lik);
    lik = fmaf(w2, comp_prob(m2, t, s2), lik);

    bool paid = (t > 0.f);
    float ll = __logf(lik + EPS);
    if (paid) { a.ll += ll; a.np += 1.f; }

    float q = paid ? p : (1.f - p);
    a.p -= fmaxf(__logf(q), -100.f);
}

// 1D TMA bulk copy: gmem -> smem, completion via mbarrier complete_tx.
__device__ __forceinline__ void bulk_cp(uint32_t dst, const void* src,
                                        uint32_t bytes, uint32_t mbar) {
    asm volatile(
        "cp.async.bulk.shared::cta.global.mbarrier::complete_tx::bytes "
        "[%0], [%1], %2, [%3];"
        :: "r"(dst), "l"(src), "r"(bytes), "r"(mbar) : "memory");
}

__device__ __forceinline__ void mbar_wait(uint32_t mbar, uint32_t parity) {
    asm volatile(
        "{\n\t"
        ".reg .pred P;\n\t"
        "W%=:\n\t"
        "mbarrier.try_wait.parity.acquire.cta.shared::cta.b64 P, [%0], %1, 0x989680;\n\t"
        "@P bra D%=;\n\t"
        "bra W%=;\n\t"
        "D%=:\n\t"
        "}"
        :: "r"(mbar), "r"(parity) : "memory");
}

__global__ void __launch_bounds__(NTHR, 1) zimol_fused(
    const float* __restrict__ pp, const float* __restrict__ mu,
    const float* __restrict__ sg, const float* __restrict__ wt,
    const float* __restrict__ tv, float* __restrict__ out, int B)
{
    extern __shared__ float2 sbuf[];   // [NSTAGE][ARRS][NTHR]
    __shared__ __align__(8) uint64_t mbar_full[NSTAGE];

    const int nvec2  = B >> 1;                        // float2 elements per row
    const int ntiles = (nvec2 + NTHR - 1) / NTHR;     // tiles of NTHR float2
    const int tid = threadIdx.x;
    const int bid = blockIdx.x;
    const int mk  = (bid < ntiles) ? (ntiles - bid + NBLK - 1) / NBLK : 0;

    const float2* pp2 = reinterpret_cast<const float2*>(pp);
    const float2* tv2 = reinterpret_cast<const float2*>(tv);
    const float2* mu2 = reinterpret_cast<const float2*>(mu);
    const float2* sg2 = reinterpret_cast<const float2*>(sg);
    const float2* wt2 = reinterpret_cast<const float2*>(wt);

    const uint32_t smem0 = (uint32_t)__cvta_generic_to_shared(sbuf);
    const uint32_t mbar0 = (uint32_t)__cvta_generic_to_shared(mbar_full);

    if (tid == 0) {
        #pragma unroll
        for (int s = 0; s < NSTAGE; s++)
            asm volatile("mbarrier.init.shared.b64 [%0], 1;"
                         :: "r"(mbar0 + s * 8) : "memory");
        asm volatile("fence.proxy.async.shared::cta;" ::: "memory");
    }
    __syncthreads();

    Acc a = {0.f, 0.f, 0.f};

    // Producer: thread 0 issues one stage (11 contiguous 4KB bulk copies).
    auto issue = [&](int t) {
        int tile = bid + t * NBLK;
        long base = (long)tile * NTHR;              // float2 offset
        uint32_t mb = mbar0 + (t & (NSTAGE - 1)) * 8;
        if (base + NTHR <= nvec2) {                 // full tile: TMA path
            uint32_t d = smem0 + (uint32_t)(t & (NSTAGE - 1)) * STAGE_BYTES;
            const uint32_t CB = NTHR * 8u;          // bytes per array chunk
            asm volatile("mbarrier.arrive.expect_tx.shared.b64 _, [%0], %1;"
                         :: "r"(mb), "r"((uint32_t)STAGE_BYTES) : "memory");
            bulk_cp(d + 0u  * CB, pp2 + base,             CB, mb);
            bulk_cp(d + 1u  * CB, tv2 + base,             CB, mb);
            bulk_cp(d + 2u  * CB, mu2 + base,             CB, mb);
            bulk_cp(d + 3u  * CB, mu2 + nvec2 + base,     CB, mb);
            bulk_cp(d + 4u  * CB, mu2 + 2 * nvec2 + base, CB, mb);
            bulk_cp(d + 5u  * CB, sg2 + base,             CB, mb);
            bulk_cp(d + 6u  * CB, sg2 + nvec2 + base,     CB, mb);
            bulk_cp(d + 7u  * CB, sg2 + 2 * nvec2 + base, CB, mb);
            bulk_cp(d + 8u  * CB, wt2 + base,             CB, mb);
            bulk_cp(d + 9u  * CB, wt2 + nvec2 + base,     CB, mb);
            bulk_cp(d + 10u * CB, wt2 + 2 * nvec2 + base, CB, mb);
        } else {                                    // ragged tile: no tx, gmem path
            asm volatile("mbarrier.arrive.shared.b64 _, [%0];"
                         :: "r"(mb) : "memory");
        }
    };

    auto compute_stage = [&](int k) {
        int tile = bid + k * NBLK;
        long v = (long)tile * NTHR + tid;
        if (v >= nvec2) return;
        if ((long)tile * NTHR + NTHR <= nvec2) {    // data staged in smem
            const float2* sb = sbuf + (k & (NSTAGE - 1)) * STAGE_F2 + tid;
            float2 P  = sb[0 * NTHR], T  = sb[1 * NTHR];
            float2 M0 = sb[2 * NTHR], M1 = sb[3 * NTHR], M2 = sb[4 * NTHR];
            float2 S0 = sb[5 * NTHR], S1 = sb[6 * NTHR], S2 = sb[7 * NTHR];
            float2 W0 = sb[8 * NTHR], W1 = sb[9 * NTHR], W2 = sb[10 * NTHR];
            process_elem(P.x, T.x, M0.x, S0.x, W0.x,
                         M1.x, S1.x, W1.x, M2.x, S2.x, W2.x, a);
            process_elem(P.y, T.y, M0.y, S0.y, W0.y,
                         M1.y, S1.y, W1.y, M2.y, S2.y, W2.y, a);
        } else {                                    // ragged tile: direct gmem
            float2 P  = __ldg(pp2 + v), T = __ldg(tv2 + v);
            float2 M0 = __ldg(mu2 + v), M1 = __ldg(mu2 + nvec2 + v), M2 = __ldg(mu2 + 2 * nvec2 + v);
            float2 S0 = __ldg(sg2 + v), S1 = __ldg(sg2 + nvec2 + v), S2 = __ldg(sg2 + 2 * nvec2 + v);
            float2 W0 = __ldg(wt2 + v), W1 = __ldg(wt2 + nvec2 + v), W2 = __ldg(wt2 + 2 * nvec2 + v);
            process_elem(P.x, T.x, M0.x, S0.x, W0.x,
                         M1.x, S1.x, W1.x, M2.x, S2.x, W2.x, a);
            process_elem(P.y, T.y, M0.y, S0.y, W0.y,
                         M1.y, S1.y, W1.y, M2.y, S2.y, W2.y, a);
        }
    };

    // ---- 4-stage TMA-bulk ring; __syncthreads gates slot reuse ----
    if (tid == 0) {
        #pragma unroll
        for (int s = 0; s < NSTAGE; s++) if (s < mk) issue(s);
    }
    for (int k = 0; k < mk; k++) {
        mbar_wait(mbar0 + (k & (NSTAGE - 1)) * 8, (k / NSTAGE) & 1);
        compute_stage(k);
        __syncthreads();                            // all reads of slot done
        if (tid == 0 && k + NSTAGE < mk) issue(k + NSTAGE);
    }

    // Scalar tail (B odd) — robustness; no-op for B = 4M.
    if ((B & 1) && bid == 0 && tid == 0) {
        int j = nvec2 << 1;
        process_elem(pp[j], tv[j],
                     mu[0 * B + j], sg[0 * B + j], wt[0 * B + j],
                     mu[1 * B + j], sg[1 * B + j], wt[1 * B + j],
                     mu[2 * B + j], sg[2 * B + j], wt[2 * B + j], a);
    }

    // ---- Block reduction (all float, shuffle + tiny smem) ----
    #pragma unroll
    for (int o = 16; o > 0; o >>= 1) {
        a.p  += __shfl_down_sync(0xffffffffu, a.p,  o);
        a.ll += __shfl_down_sync(0xffffffffu, a.ll, o);
        a.np += __shfl_down_sync(0xffffffffu, a.np, o);
    }

    __shared__ float shp[NWARP], shl[NWARP], shn[NWARP];
    __shared__ bool s_last;
    int wid  = tid >> 5;
    int lane = tid & 31;
    if (lane == 0) { shp[wid] = a.p; shl[wid] = a.ll; shn[wid] = a.np; }
    __syncthreads();

    if (tid == 0) {
        float vp = 0.f, vl = 0.f, vn = 0.f;
        #pragma unroll
        for (int k = 0; k < NWARP; k++) { vp += shp[k]; vl += shl[k]; vn += shn[k]; }
        g_part_p[bid]  = vp;
        g_part_ll[bid] = vl;
        g_part_np[bid] = vn;
        __threadfence();
        unsigned t = atomicAdd(&g_ticket, 1u);
        s_last = (t == (unsigned)(NBLK - 1));
        if (s_last) g_ticket = 0u;   // self-reset: deterministic across replays
    }
    __syncthreads();

    // ---- Last block finalizes (float, 148 partials) ----
    if (s_last) {
        float sp = 0.f, sl = 0.f, sn = 0.f;
        for (int k = tid; k < NBLK; k += NTHR) {
            sp += g_part_p[k];
            sl += g_part_ll[k];
            sn += g_part_np[k];
        }
        #pragma unroll
        for (int o = 16; o > 0; o >>= 1) {
            sp += __shfl_down_sync(0xffffffffu, sp, o);
            sl += __shfl_down_sync(0xffffffffu, sl, o);
            sn += __shfl_down_sync(0xffffffffu, sn, o);
        }
        if (lane == 0) { shp[wid] = sp; shl[wid] = sl; shn[wid] = sn; }
        __syncthreads();
        if (tid == 0) {
            float vp = 0.f, vl = 0.f, vn = 0.f;
            #pragma unroll
            for (int k = 0; k < NWARP; k++) { vp += shp[k]; vl += shl[k]; vn += shn[k]; }
            float purchase = vp / (float)B;
            float ltv = (vn > 0.f) ? -(vl / fmaxf(vn, 1.f)) : 0.f;
            out[0] = purchase + ltv;
        }
    }
}

extern "C" void kernel_launch(void* const* d_in, const int* in_sizes, int n_in,
                              void* d_out, int out_size)
{
    const float* pp = (const float*)d_in[0];  // predicted_purchase_prob (B,)
    const float* mu = (const float*)d_in[1];  // mu     (K,B)
    const float* sg = (const float*)d_in[2];  // sigma  (K,B)
    const float* wt = (const float*)d_in[3];  // weight (K,B)
    const float* tv = (const float*)d_in[4];  // true_values (B,)
    int B = in_sizes[0];

    // Opt-in to 176 KB dynamic smem (idempotent; not a stream op).
    cudaFuncSetAttribute(zimol_fused,
                         cudaFuncAttributeMaxDynamicSharedMemorySize, SMEM_BYTES);
    zimol_fused<<<NBLK, NTHR, SMEM_BYTES>>>(pp, mu, sg, wt, tv, (float*)d_out, B);
}